// round 2
// baseline (speedup 1.0000x reference)
#include <cuda_runtime.h>
#include <cstdint>
#include <math.h>

#define T_LEN 2048
#define BSZ   32
#define DIM   256
#define HID   256
#define LAY   2

// Scratch: gx[t][l][gate3][b][h]  (2048*2*3*32*256 floats = 402MB)
__device__ float g_gx[(size_t)T_LEN * LAY * 3 * BSZ * HID];

// ---------------------------------------------------------------------------
// Kernel 1: gx GEMM.  C[m][n] = sum_k x[m][k]*Wx[n][k] + bx[n]
//   m = b*T + t (65536 rows), n = l*768 + g (1536 cols), k = 256
// Scatter into g_gx[t][l][g3][b][h].
// ---------------------------------------------------------------------------
#define APAD 260   // padded row stride in floats (16B aligned, conflict-free)

__global__ __launch_bounds__(256, 1)
void gx_gemm_kernel(const float* __restrict__ x, const float* __restrict__ Wx,
                    const float* __restrict__ bx)
{
    extern __shared__ float sm1[];
    float* sA = sm1;             // [64][APAD]  rows of x   (k contiguous)
    float* sB = sm1 + 64 * APAD; // [64][APAD]  rows of Wx  (k contiguous)

    const int tid = threadIdx.x;
    const int tx  = tid & 15;    // output col group
    const int ty  = tid >> 4;    // output row group
    const int nbase = blockIdx.x * 64;

    // Load B panel once (64 cols x 256 k) as float4
    for (int idx = tid; idx < 64 * 64; idx += 256) {
        int j = idx >> 6, k4 = idx & 63;
        float4 v = *reinterpret_cast<const float4*>(
            Wx + (((size_t)(nbase + j)) << 8) + (k4 << 2));
        *reinterpret_cast<float4*>(sB + j * APAD + (k4 << 2)) = v;
    }

    int   ncol[4];
    float bias[4];
#pragma unroll
    for (int jj = 0; jj < 4; jj++) {
        ncol[jj] = nbase + tx + 16 * jj;
        bias[jj] = bx[ncol[jj]];
    }
    __syncthreads();

    for (int ms = 0; ms < 8; ms++) {
        const int mbase = (blockIdx.y * 8 + ms) * 64;
        for (int idx = tid; idx < 64 * 64; idx += 256) {
            int r = idx >> 6, k4 = idx & 63;
            float4 v = *reinterpret_cast<const float4*>(
                x + (((size_t)(mbase + r)) << 8) + (k4 << 2));
            *reinterpret_cast<float4*>(sA + r * APAD + (k4 << 2)) = v;
        }
        __syncthreads();

        float acc[4][4];
#pragma unroll
        for (int i = 0; i < 4; i++)
#pragma unroll
            for (int j = 0; j < 4; j++) acc[i][j] = 0.f;

#pragma unroll 2
        for (int k4 = 0; k4 < 64; k4++) {
            float4 av[4], bv[4];
#pragma unroll
            for (int ii = 0; ii < 4; ii++)
                av[ii] = *reinterpret_cast<const float4*>(sA + (ty * 4 + ii) * APAD + (k4 << 2));
#pragma unroll
            for (int jj = 0; jj < 4; jj++)
                bv[jj] = *reinterpret_cast<const float4*>(sB + (tx + 16 * jj) * APAD + (k4 << 2));
#pragma unroll
            for (int ii = 0; ii < 4; ii++)
#pragma unroll
                for (int jj = 0; jj < 4; jj++) {
                    acc[ii][jj] = fmaf(av[ii].x, bv[jj].x, acc[ii][jj]);
                    acc[ii][jj] = fmaf(av[ii].y, bv[jj].y, acc[ii][jj]);
                    acc[ii][jj] = fmaf(av[ii].z, bv[jj].z, acc[ii][jj]);
                    acc[ii][jj] = fmaf(av[ii].w, bv[jj].w, acc[ii][jj]);
                }
        }

        // scatter into g_gx[t][l][g3][b][h]
#pragma unroll
        for (int jj = 0; jj < 4; jj++) {
            const int n  = ncol[jj];
            const int l  = n / 768;
            const int rr = n - l * 768;
            const int g3 = rr >> 8;
            const int h  = rr & 255;
#pragma unroll
            for (int ii = 0; ii < 4; ii++) {
                const int m = mbase + ty * 4 + ii;
                const int b = m >> 11;      // / T_LEN
                const int t = m & 2047;     // % T_LEN
                const size_t o =
                    ((((size_t)t * LAY + l) * 3 + g3) * BSZ + b) * HID + h;
                g_gx[o] = acc[ii][jj] + bias[jj];
            }
        }
        __syncthreads();
    }
}

// ---------------------------------------------------------------------------
// Kernel 2: cluster-persistent bidirectional GRU scan.
// 128 CTAs = 4 (layer,dir) groups x 8 batch-chunks(4 batches) x 4-CTA cluster.
// Cluster rank r owns h-slice [r*64, r*64+64): holds Wh rows
// {g*256 + r*64 .. +64 | g=0..2} (192 rows) in smem; full h (4 x 256, double
// buffered) replicated per CTA via st.shared::cluster; one cluster barrier/step.
// ---------------------------------------------------------------------------
#define WH_PAD     260
#define SC_THREADS 192

__device__ __forceinline__ void st_cluster_f32(uint32_t saddr, int trank, float v)
{
    uint32_t ra;
    asm volatile("mapa.shared::cluster.u32 %0, %1, %2;" : "=r"(ra) : "r"(saddr), "r"(trank));
    asm volatile("st.shared::cluster.f32 [%0], %1;" :: "r"(ra), "f"(v) : "memory");
}

__device__ __forceinline__ void cluster_barrier()
{
    asm volatile("barrier.cluster.arrive.aligned;\n\tbarrier.cluster.wait.aligned;" ::: "memory");
}

__device__ __forceinline__ float sigmoidf_(float v) { return 1.f / (1.f + expf(-v)); }

__global__ void __cluster_dims__(4, 1, 1) __launch_bounds__(SC_THREADS, 1)
gru_scan_kernel(const float* __restrict__ Wh, const float* __restrict__ bh,
                float* __restrict__ out)
{
    extern __shared__ float sm[];
    float* sWh   = sm;                       // [192][WH_PAD]
    float* hbuf  = sm + 192 * WH_PAD;        // [2][4][256]
    float* ex_z  = hbuf + 2 * 4 * 256;       // [4][64]
    float* ex_xn = ex_z + 256;               // [4][64]
    float* ex_hn = ex_xn + 256;              // [4][64]

    const int tid  = threadIdx.x;
    const int rank = blockIdx.x & 3;         // cluster rank (contiguous mapping)
    const int cg   = blockIdx.x >> 2;        // global cluster id 0..31
    const int g    = cg >> 3;                // (layer,dir) group 0..3
    const int c    = cg & 7;                 // batch chunk 0..7
    const int l    = g >> 1;
    const int dir  = g & 1;
    const int b0   = c * 4;
    const int gi   = tid / 64;               // gate 0=r,1=z,2=n
    const int li   = tid & 63;
    const int hi   = rank * 64 + li;         // owned h index

    // Load Wh slice: thread's own row (gate gi, h-row hi), 256 floats
    {
        const float* wrow = Wh + (size_t)l * 768 * 256 + ((size_t)gi * 256 + hi) * 256;
        const float4* src = reinterpret_cast<const float4*>(wrow);
        float4* dst = reinterpret_cast<float4*>(sWh + tid * WH_PAD);
#pragma unroll 8
        for (int k4 = 0; k4 < 64; k4++) dst[k4] = src[k4];
    }
    for (int i = tid; i < 2 * 4 * 256; i += SC_THREADS) hbuf[i] = 0.f;

    const float bhv = bh[l * 768 + gi * 256 + hi];

    __syncthreads();
    cluster_barrier();   // everyone's smem initialized before any remote write

    const uint32_t hbuf_saddr = (uint32_t)__cvta_generic_to_shared(hbuf);

    float hprev[4] = {0.f, 0.f, 0.f, 0.f};   // valid for gi==0 threads
    int p = 0;

    for (int step = 0; step < T_LEN; step++) {
        const int t = dir ? (T_LEN - 1 - step) : step;

        // Prefetch this thread's gx (its own gate) for 4 batches
        float gx[4];
        {
            const size_t base = ((((size_t)t * LAY + l) * 3 + gi) * BSZ + b0) * HID + hi;
#pragma unroll
            for (int b = 0; b < 4; b++) gx[b] = __ldg(g_gx + base + (size_t)b * HID);
        }

        // gh[b] = h[b] . Wh_row + bh   (256-long dot, 4 batches)
        float acc[4] = {bhv, bhv, bhv, bhv};
        {
            const float4* wrow = reinterpret_cast<const float4*>(sWh + tid * WH_PAD);
            const float4* h0 = reinterpret_cast<const float4*>(hbuf + (p * 4 + 0) * 256);
            const float4* h1 = reinterpret_cast<const float4*>(hbuf + (p * 4 + 1) * 256);
            const float4* h2 = reinterpret_cast<const float4*>(hbuf + (p * 4 + 2) * 256);
            const float4* h3 = reinterpret_cast<const float4*>(hbuf + (p * 4 + 3) * 256);
#pragma unroll 8
            for (int k4 = 0; k4 < 64; k4++) {
                const float4 w  = wrow[k4];
                const float4 va = h0[k4];
                const float4 vb = h1[k4];
                const float4 vc = h2[k4];
                const float4 vd = h3[k4];
                acc[0] = fmaf(w.x, va.x, acc[0]); acc[0] = fmaf(w.y, va.y, acc[0]);
                acc[0] = fmaf(w.z, va.z, acc[0]); acc[0] = fmaf(w.w, va.w, acc[0]);
                acc[1] = fmaf(w.x, vb.x, acc[1]); acc[1] = fmaf(w.y, vb.y, acc[1]);
                acc[1] = fmaf(w.z, vb.z, acc[1]); acc[1] = fmaf(w.w, vb.w, acc[1]);
                acc[2] = fmaf(w.x, vc.x, acc[2]); acc[2] = fmaf(w.y, vc.y, acc[2]);
                acc[2] = fmaf(w.z, vc.z, acc[2]); acc[2] = fmaf(w.w, vc.w, acc[2]);
                acc[3] = fmaf(w.x, vd.x, acc[3]); acc[3] = fmaf(w.y, vd.y, acc[3]);
                acc[3] = fmaf(w.z, vd.z, acc[3]); acc[3] = fmaf(w.w, vd.w, acc[3]);
            }
        }

        // Phase A: gate nonlinearity / exchange
        float rv[4];
        if (gi == 0) {
#pragma unroll
            for (int b = 0; b < 4; b++) rv[b] = sigmoidf_(gx[b] + acc[b]);
        } else if (gi == 1) {
#pragma unroll
            for (int b = 0; b < 4; b++) ex_z[b * 64 + li] = sigmoidf_(gx[b] + acc[b]);
        } else {
#pragma unroll
            for (int b = 0; b < 4; b++) { ex_xn[b * 64 + li] = gx[b]; ex_hn[b * 64 + li] = acc[b]; }
        }
        __syncthreads();

        // Phase B: gi==0 threads finish h_new, write out + broadcast to cluster
        if (gi == 0) {
#pragma unroll
            for (int b = 0; b < 4; b++) {
                const float n  = tanhf(ex_xn[b * 64 + li] + rv[b] * ex_hn[b * 64 + li]);
                const float z  = ex_z[b * 64 + li];
                const float hn = (1.f - z) * n + z * hprev[b];
                hprev[b] = hn;
                out[((size_t)(b0 + b) * (T_LEN * LAY) + (size_t)t * LAY + l) * (2 * HID)
                    + dir * HID + hi] = hn;
                const uint32_t la = hbuf_saddr
                    + (uint32_t)((((1 - p) * 4 + b) * 256 + hi) * 4);
#pragma unroll
                for (int r2 = 0; r2 < 4; r2++) st_cluster_f32(la, r2, hn);
            }
        }
        cluster_barrier();   // h_new visible cluster-wide; also orders exch reuse
        p ^= 1;
    }
}

// ---------------------------------------------------------------------------
extern "C" void kernel_launch(void* const* d_in, const int* in_sizes, int n_in,
                              void* d_out, int out_size)
{
    (void)in_sizes; (void)n_in; (void)out_size;
    const float* x  = (const float*)d_in[0];
    const float* Wx = (const float*)d_in[1];
    const float* Wh = (const float*)d_in[2];
    const float* bx = (const float*)d_in[3];
    const float* bh = (const float*)d_in[4];
    float* out = (float*)d_out;

    const int smem1 = 2 * 64 * APAD * 4;                         // 133,120 B
    const int smem2 = (192 * WH_PAD + 2 * 4 * 256 + 3 * 256) * 4; // 210,944 B

    cudaFuncSetAttribute(gx_gemm_kernel, cudaFuncAttributeMaxDynamicSharedMemorySize, smem1);
    cudaFuncSetAttribute(gru_scan_kernel, cudaFuncAttributeMaxDynamicSharedMemorySize, smem2);

    dim3 grid1(1536 / 64, 128);   // 24 x 128 CTAs
    gx_gemm_kernel<<<grid1, 256, smem1>>>(x, Wx, bx);

    gru_scan_kernel<<<128, SC_THREADS, smem2>>>(Wh, bh, out);
}

// round 3
// speedup vs baseline: 1.1487x; 1.1487x over previous
#include <cuda_runtime.h>
#include <cstdint>
#include <math.h>

#define T_LEN 2048
#define BSZ   32
#define DIM   256
#define HID   256
#define LAY   2

typedef unsigned long long ull;

// Scratch: gx[t][l][gate3][b][h]  (2048*2*3*32*256 floats = 402MB)
__device__ float g_gx[(size_t)T_LEN * LAY * 3 * BSZ * HID];

__device__ __forceinline__ void ffma2(ull& d, ull a, ull b) {
    asm("fma.rn.f32x2 %0, %1, %2, %0;" : "+l"(d) : "l"(a), "l"(b));
}
__device__ __forceinline__ ull splat2(float v) {
    ull r; asm("mov.b64 %0, {%1, %1};" : "=l"(r) : "f"(v)); return r;
}
__device__ __forceinline__ float2 unpack2(ull v) {
    float2 r; asm("mov.b64 {%0, %1}, %2;" : "=f"(r.x), "=f"(r.y) : "l"(v)); return r;
}

// ---------------------------------------------------------------------------
// Kernel 1: gx GEMM.  C[m][n] = sum_k x[m][k]*Wx[n][k] + bx[n]
//   m = b*T + t (65536 rows), n = l*768 + g (1536 cols), k = 256
// f32x2-packed over k-parity (float4 loads give packed pairs for free).
// ---------------------------------------------------------------------------
#define APAD 260

__global__ __launch_bounds__(256, 1)
void gx_gemm_kernel(const float* __restrict__ x, const float* __restrict__ Wx,
                    const float* __restrict__ bx)
{
    extern __shared__ float sm1[];
    float* sA = sm1;             // [64][APAD]  rows of x
    float* sB = sm1 + 64 * APAD; // [64][APAD]  rows of Wx

    const int tid = threadIdx.x;
    const int tx  = tid & 15;
    const int ty  = tid >> 4;
    const int nbase = blockIdx.x * 64;

    for (int idx = tid; idx < 64 * 64; idx += 256) {
        int j = idx >> 6, k4 = idx & 63;
        float4 v = *reinterpret_cast<const float4*>(
            Wx + (((size_t)(nbase + j)) << 8) + (k4 << 2));
        *reinterpret_cast<float4*>(sB + j * APAD + (k4 << 2)) = v;
    }

    int   ncol[4];
    float bias[4];
#pragma unroll
    for (int jj = 0; jj < 4; jj++) {
        ncol[jj] = nbase + tx + 16 * jj;
        bias[jj] = bx[ncol[jj]];
    }
    __syncthreads();

    for (int ms = 0; ms < 8; ms++) {
        const int mbase = (blockIdx.y * 8 + ms) * 64;
        for (int idx = tid; idx < 64 * 64; idx += 256) {
            int r = idx >> 6, k4 = idx & 63;
            float4 v = *reinterpret_cast<const float4*>(
                x + (((size_t)(mbase + r)) << 8) + (k4 << 2));
            *reinterpret_cast<float4*>(sA + r * APAD + (k4 << 2)) = v;
        }
        __syncthreads();

        ull acc2[4][4];
#pragma unroll
        for (int i = 0; i < 4; i++)
#pragma unroll
            for (int j = 0; j < 4; j++) acc2[i][j] = 0ull;

#pragma unroll 2
        for (int k4 = 0; k4 < 64; k4++) {
            ulonglong2 av[4], bv[4];
#pragma unroll
            for (int ii = 0; ii < 4; ii++)
                av[ii] = *reinterpret_cast<const ulonglong2*>(sA + (ty * 4 + ii) * APAD + (k4 << 2));
#pragma unroll
            for (int jj = 0; jj < 4; jj++)
                bv[jj] = *reinterpret_cast<const ulonglong2*>(sB + (tx + 16 * jj) * APAD + (k4 << 2));
#pragma unroll
            for (int ii = 0; ii < 4; ii++)
#pragma unroll
                for (int jj = 0; jj < 4; jj++) {
                    ffma2(acc2[ii][jj], av[ii].x, bv[jj].x);
                    ffma2(acc2[ii][jj], av[ii].y, bv[jj].y);
                }
        }

#pragma unroll
        for (int jj = 0; jj < 4; jj++) {
            const int n  = ncol[jj];
            const int l  = n / 768;
            const int rr = n - l * 768;
            const int g3 = rr >> 8;
            const int h  = rr & 255;
#pragma unroll
            for (int ii = 0; ii < 4; ii++) {
                const int m = mbase + ty * 4 + ii;
                const int b = m >> 11;
                const int t = m & 2047;
                float2 s = unpack2(acc2[ii][jj]);
                const size_t o =
                    ((((size_t)t * LAY + l) * 3 + g3) * BSZ + b) * HID + h;
                g_gx[o] = s.x + s.y + bias[jj];
            }
        }
        __syncthreads();
    }
}

// ---------------------------------------------------------------------------
// Kernel 2: cluster-persistent bidirectional GRU scan.
// 128 CTAs = 4 (layer,dir) groups x 8 batch-chunks(4 batches) x 4-CTA cluster.
// Thread (gi,li): gate gi row hi=rank*64+li; w[k<64] in regs, w[k>=64] smem.
// h stored as hbuf[p][k][b0..b3] (float4 per k) -> batch-pair f32x2 FMA.
// ---------------------------------------------------------------------------
#define RSTR       196     // smem row stride for the 192 remaining w floats
#define SC_THREADS 192

__device__ __forceinline__ void st_cluster_v2(uint32_t saddr, int trank, float v0, float v1)
{
    uint32_t ra;
    asm volatile("mapa.shared::cluster.u32 %0, %1, %2;" : "=r"(ra) : "r"(saddr), "r"(trank));
    asm volatile("st.shared::cluster.v2.f32 [%0], {%1, %2};" :: "r"(ra), "f"(v0), "f"(v1) : "memory");
}
__device__ __forceinline__ void cluster_barrier()
{
    asm volatile("barrier.cluster.arrive.aligned;\n\tbarrier.cluster.wait.aligned;" ::: "memory");
}
__device__ __forceinline__ float sig_fast(float x) {
    return __fdividef(1.f, 1.f + __expf(-x));
}
__device__ __forceinline__ float tanh_fast(float x) {
    x = fminf(fmaxf(x, -15.f), 15.f);
    float e = __expf(2.f * x);
    return __fdividef(e - 1.f, e + 1.f);
}

__global__ void __cluster_dims__(4, 1, 1) __launch_bounds__(SC_THREADS, 1)
gru_scan_kernel(const float* __restrict__ Wh, const float* __restrict__ bh,
                float* __restrict__ out)
{
    extern __shared__ float sm[];
    float* sWh   = sm;                         // [192 threads][RSTR] (k=64..255)
    float* hbuf  = sm + SC_THREADS * RSTR;     // [2][256][4]  (k, batch) packed
    float* ex_r  = hbuf + 2 * 256 * 4;         // [4][64]
    float* ex_z  = ex_r + 256;                 // [4][64]
    float* ex_xn = ex_z + 256;                 // [4][64]
    float* ex_hn = ex_xn + 256;                // [4][64]

    const int tid  = threadIdx.x;
    const int rank = blockIdx.x & 3;
    const int cg   = blockIdx.x >> 2;
    const int g    = cg >> 3;
    const int c    = cg & 7;
    const int l    = g >> 1;
    const int dir  = g & 1;
    const int b0   = c * 4;
    const int gi   = tid / 64;                 // gate 0=r,1=z,2=n (warp-uniform)
    const int li   = tid & 63;
    const int hi   = rank * 64 + li;

    // Wh row for (gate gi, row hi): k 0..63 into regs, k 64..255 into smem.
    const float* wrow = Wh + (size_t)l * 768 * 256 + ((size_t)gi * 256 + hi) * 256;
    float4 wreg[16];
#pragma unroll
    for (int i = 0; i < 16; i++)
        wreg[i] = reinterpret_cast<const float4*>(wrow)[i];
    {
        float4* dst = reinterpret_cast<float4*>(sWh + tid * RSTR);
#pragma unroll 8
        for (int i = 0; i < 48; i++)
            dst[i] = reinterpret_cast<const float4*>(wrow)[16 + i];
    }
    for (int i = tid; i < 2 * 256 * 4; i += SC_THREADS) hbuf[i] = 0.f;

    const float bhv = bh[l * 768 + gi * 256 + hi];

    __syncthreads();
    cluster_barrier();

    const uint32_t hbuf_saddr = (uint32_t)__cvta_generic_to_shared(hbuf);

    float hprev0 = 0.f, hprev1 = 0.f;   // gi0: b0,b1 ; gi1: b2,b3
    int p = 0;

    for (int step = 0; step < T_LEN; step++) {
        const int t = dir ? (T_LEN - 1 - step) : step;

        // gx for this thread's gate, 4 batches (latency hidden under the dot)
        float gx[4];
        {
            const size_t base = ((((size_t)t * LAY + l) * 3 + gi) * BSZ + b0) * HID + hi;
#pragma unroll
            for (int b = 0; b < 4; b++) gx[b] = __ldg(g_gx + base + (size_t)b * HID);
        }

        // gh = h . w + bh, batch-pair packed f32x2
        ull a01 = splat2(bhv), a23 = splat2(bhv);
        const ulonglong2* hp = reinterpret_cast<const ulonglong2*>(hbuf) + p * 256;

#pragma unroll
        for (int k4 = 0; k4 < 16; k4++) {       // k in regs
            const float4 w = wreg[k4];
            const float wf[4] = {w.x, w.y, w.z, w.w};
#pragma unroll
            for (int j = 0; j < 4; j++) {
                ulonglong2 hk = hp[k4 * 4 + j]; // broadcast, (b0b1),(b2b3)
                ull w2 = splat2(wf[j]);
                ffma2(a01, w2, hk.x);
                ffma2(a23, w2, hk.y);
            }
        }
        {
            const float4* wsm = reinterpret_cast<const float4*>(sWh + tid * RSTR);
#pragma unroll 4
            for (int k4 = 16; k4 < 64; k4++) {  // k in smem
                const float4 w = wsm[k4 - 16];
                const float wf[4] = {w.x, w.y, w.z, w.w};
#pragma unroll
                for (int j = 0; j < 4; j++) {
                    ulonglong2 hk = hp[k4 * 4 + j];
                    ull w2 = splat2(wf[j]);
                    ffma2(a01, w2, hk.x);
                    ffma2(a23, w2, hk.y);
                }
            }
        }
        float2 s01 = unpack2(a01), s23 = unpack2(a23);
        float acc[4] = {s01.x, s01.y, s23.x, s23.y};

        // Phase A: gate nonlinearity + exchange
        float v0, v1;                  // gi0: r(b0),r(b1) ; gi1: z(b2),z(b3)
        if (gi == 0) {
            float r0 = sig_fast(gx[0] + acc[0]);
            float r1 = sig_fast(gx[1] + acc[1]);
            float r2 = sig_fast(gx[2] + acc[2]);
            float r3 = sig_fast(gx[3] + acc[3]);
            v0 = r0; v1 = r1;
            ex_r[2 * 64 + li] = r2; ex_r[3 * 64 + li] = r3;
        } else if (gi == 1) {
            float z0 = sig_fast(gx[0] + acc[0]);
            float z1 = sig_fast(gx[1] + acc[1]);
            float z2 = sig_fast(gx[2] + acc[2]);
            float z3 = sig_fast(gx[3] + acc[3]);
            v0 = z2; v1 = z3;
            ex_z[0 * 64 + li] = z0; ex_z[1 * 64 + li] = z1;
        } else {
#pragma unroll
            for (int b = 0; b < 4; b++) {
                ex_xn[b * 64 + li] = gx[b];
                ex_hn[b * 64 + li] = acc[b];
            }
        }
        __syncthreads();

        // Phase B: combine. gi0 handles b0,b1 ; gi1 handles b2,b3.
        if (gi < 2) {
            const int ba = (gi == 0) ? 0 : 2;
            float r_a, r_b, z_a, z_b;
            if (gi == 0) { r_a = v0; r_b = v1; z_a = ex_z[0 * 64 + li]; z_b = ex_z[1 * 64 + li]; }
            else         { r_a = ex_r[2 * 64 + li]; r_b = ex_r[3 * 64 + li]; z_a = v0; z_b = v1; }

            const float n_a = tanh_fast(ex_xn[(ba + 0) * 64 + li] + r_a * ex_hn[(ba + 0) * 64 + li]);
            const float n_b = tanh_fast(ex_xn[(ba + 1) * 64 + li] + r_b * ex_hn[(ba + 1) * 64 + li]);
            const float h_a = (1.f - z_a) * n_a + z_a * hprev0;
            const float h_b = (1.f - z_b) * n_b + z_b * hprev1;
            hprev0 = h_a; hprev1 = h_b;

            const size_t obase = ((size_t)t * LAY + l) * (2 * HID) + dir * HID + hi;
            out[(size_t)(b0 + ba + 0) * (T_LEN * LAY * 2 * HID) + obase] = h_a;
            out[(size_t)(b0 + ba + 1) * (T_LEN * LAY * 2 * HID) + obase] = h_b;

            // broadcast packed pair into all 4 ranks' hbuf[1-p][hi][ba..ba+1]
            const uint32_t la = hbuf_saddr
                + (uint32_t)((((1 - p) * 256 + hi) * 4 + ba) * 4);
#pragma unroll
            for (int r2 = 0; r2 < 4; r2++) st_cluster_v2(la, r2, h_a, h_b);
        }
        cluster_barrier();
        p ^= 1;
    }
}

// ---------------------------------------------------------------------------
extern "C" void kernel_launch(void* const* d_in, const int* in_sizes, int n_in,
                              void* d_out, int out_size)
{
    (void)in_sizes; (void)n_in; (void)out_size;
    const float* x  = (const float*)d_in[0];
    const float* Wx = (const float*)d_in[1];
    const float* Wh = (const float*)d_in[2];
    const float* bx = (const float*)d_in[3];
    const float* bh = (const float*)d_in[4];
    float* out = (float*)d_out;

    const int smem1 = 2 * 64 * APAD * 4;                                    // 133,120 B
    const int smem2 = (SC_THREADS * RSTR + 2 * 256 * 4 + 4 * 256) * 4;      // 163,840 B

    cudaFuncSetAttribute(gx_gemm_kernel, cudaFuncAttributeMaxDynamicSharedMemorySize, smem1);
    cudaFuncSetAttribute(gru_scan_kernel, cudaFuncAttributeMaxDynamicSharedMemorySize, smem2);

    dim3 grid1(1536 / 64, 128);
    gx_gemm_kernel<<<grid1, 256, smem1>>>(x, Wx, bx);

    gru_scan_kernel<<<128, SC_THREADS, smem2>>>(Wh, bh, out);
}

// round 4
// speedup vs baseline: 1.5815x; 1.3768x over previous
#include <cuda_runtime.h>
#include <cstdint>
#include <math.h>

#define T_LEN 2048
#define BSZ   32
#define DIM   256
#define HID   256
#define LAY   2

typedef unsigned long long ull;

// Scratch: gx[t][l][gate3][b][h]  (2048*2*3*32*256 floats = 402MB)
__device__ float g_gx[(size_t)T_LEN * LAY * 3 * BSZ * HID];

__device__ __forceinline__ void ffma2(ull& d, ull a, ull b) {
    asm("fma.rn.f32x2 %0, %1, %2, %0;" : "+l"(d) : "l"(a), "l"(b));
}
__device__ __forceinline__ ull splat2(float v) {
    ull r; asm("mov.b64 %0, {%1, %1};" : "=l"(r) : "f"(v)); return r;
}
__device__ __forceinline__ float2 unpack2(ull v) {
    float2 r; asm("mov.b64 {%0, %1}, %2;" : "=f"(r.x), "=f"(r.y) : "l"(v)); return r;
}

// ---------------------------------------------------------------------------
// Kernel 1: gx GEMM.  C[m][n] = sum_k x[m][k]*Wx[n][k] + bx[n]
// ---------------------------------------------------------------------------
#define APAD 260

__global__ __launch_bounds__(256, 1)
void gx_gemm_kernel(const float* __restrict__ x, const float* __restrict__ Wx,
                    const float* __restrict__ bx)
{
    extern __shared__ float sm1[];
    float* sA = sm1;             // [64][APAD]
    float* sB = sm1 + 64 * APAD; // [64][APAD]

    const int tid = threadIdx.x;
    const int tx  = tid & 15;
    const int ty  = tid >> 4;
    const int nbase = blockIdx.x * 64;

    for (int idx = tid; idx < 64 * 64; idx += 256) {
        int j = idx >> 6, k4 = idx & 63;
        float4 v = *reinterpret_cast<const float4*>(
            Wx + (((size_t)(nbase + j)) << 8) + (k4 << 2));
        *reinterpret_cast<float4*>(sB + j * APAD + (k4 << 2)) = v;
    }

    int   ncol[4];
    float bias[4];
#pragma unroll
    for (int jj = 0; jj < 4; jj++) {
        ncol[jj] = nbase + tx + 16 * jj;
        bias[jj] = bx[ncol[jj]];
    }
    __syncthreads();

    for (int ms = 0; ms < 8; ms++) {
        const int mbase = (blockIdx.y * 8 + ms) * 64;
        for (int idx = tid; idx < 64 * 64; idx += 256) {
            int r = idx >> 6, k4 = idx & 63;
            float4 v = *reinterpret_cast<const float4*>(
                x + (((size_t)(mbase + r)) << 8) + (k4 << 2));
            *reinterpret_cast<float4*>(sA + r * APAD + (k4 << 2)) = v;
        }
        __syncthreads();

        ull acc2[4][4];
#pragma unroll
        for (int i = 0; i < 4; i++)
#pragma unroll
            for (int j = 0; j < 4; j++) acc2[i][j] = 0ull;

#pragma unroll 2
        for (int k4 = 0; k4 < 64; k4++) {
            ulonglong2 av[4], bv[4];
#pragma unroll
            for (int ii = 0; ii < 4; ii++)
                av[ii] = *reinterpret_cast<const ulonglong2*>(sA + (ty * 4 + ii) * APAD + (k4 << 2));
#pragma unroll
            for (int jj = 0; jj < 4; jj++)
                bv[jj] = *reinterpret_cast<const ulonglong2*>(sB + (tx + 16 * jj) * APAD + (k4 << 2));
#pragma unroll
            for (int ii = 0; ii < 4; ii++)
#pragma unroll
                for (int jj = 0; jj < 4; jj++) {
                    ffma2(acc2[ii][jj], av[ii].x, bv[jj].x);
                    ffma2(acc2[ii][jj], av[ii].y, bv[jj].y);
                }
        }

#pragma unroll
        for (int jj = 0; jj < 4; jj++) {
            const int n  = ncol[jj];
            const int l  = n / 768;
            const int rr = n - l * 768;
            const int g3 = rr >> 8;
            const int h  = rr & 255;
#pragma unroll
            for (int ii = 0; ii < 4; ii++) {
                const int m = mbase + ty * 4 + ii;
                const int b = m >> 11;
                const int t = m & 2047;
                float2 s = unpack2(acc2[ii][jj]);
                const size_t o =
                    ((((size_t)t * LAY + l) * 3 + g3) * BSZ + b) * HID + h;
                g_gx[o] = s.x + s.y + bias[jj];
            }
        }
        __syncthreads();
    }
}

// ---------------------------------------------------------------------------
// Kernel 2: cluster-persistent bidirectional GRU scan, split-K register tiled.
// 128 CTAs = 4 groups x 8 batch-chunks x 4-CTA cluster. 256 threads.
// Warp (rg,kc): rows rg*96 + lane*3 + {0,1,2}, k-chunk kc*64..+63.
// Rows 0,1 of the thread live in registers (128 regs); row 2 in smem plane
// w3[rg][k][lane]. Partials reduced via smem, then gate combine + cluster
// h-broadcast (one barrier.cluster per step).
// ---------------------------------------------------------------------------
#define SC_THREADS 256

__device__ __forceinline__ void st_cluster_v2(uint32_t saddr, int trank, float v0, float v1)
{
    uint32_t ra;
    asm volatile("mapa.shared::cluster.u32 %0, %1, %2;" : "=r"(ra) : "r"(saddr), "r"(trank));
    asm volatile("st.shared::cluster.v2.f32 [%0], {%1, %2};" :: "r"(ra), "f"(v0), "f"(v1) : "memory");
}
__device__ __forceinline__ void cluster_barrier()
{
    asm volatile("barrier.cluster.arrive.aligned;\n\tbarrier.cluster.wait.aligned;" ::: "memory");
}
__device__ __forceinline__ float sig_fast(float x) {
    return __fdividef(1.f, 1.f + __expf(-x));
}
__device__ __forceinline__ float tanh_fast(float x) {
    x = fminf(fmaxf(x, -15.f), 15.f);
    float e = __expf(2.f * x);
    return __fdividef(e - 1.f, e + 1.f);
}

__global__ void __cluster_dims__(4, 1, 1) __launch_bounds__(SC_THREADS, 1)
gru_scan_kernel(const float* __restrict__ Wh, const float* __restrict__ bh,
                float* __restrict__ out)
{
    extern __shared__ float sm[];
    float* sw3   = sm;                     // [2 rg][256 k][32 lane]   16384 f
    float* part  = sw3 + 2 * 256 * 32;     // [4 kc][192 rr][4 b]       3072 f
    float* hbuf  = part + 4 * 192 * 4;     // [2 p][256 k][4 b]         2048 f
    float* ex_r  = hbuf + 2 * 256 * 4;     // [4][64]
    float* ex_z  = ex_r + 256;
    float* ex_xn = ex_z + 256;
    float* ex_hn = ex_xn + 256;

    const int tid  = threadIdx.x;
    const int lane = tid & 31;
    const int wid  = tid >> 5;
    const int rg   = wid >> 2;               // row group (96 rows)
    const int kc   = wid & 3;                // k-chunk
    const int k0   = kc << 6;

    const int rank = blockIdx.x & 3;
    const int cg   = blockIdx.x >> 2;
    const int g    = cg >> 3;
    const int c    = cg & 7;
    const int l    = g >> 1;
    const int dir  = g & 1;
    const int b0   = c * 4;

    // combine-phase identity (tid < 192): rr = tid -> (gate gi, h-index hi)
    const int gi = tid >> 6;                  // 0..2 (only meaningful tid<192)
    const int li = tid & 63;
    const int hi = rank * 64 + li;

    const float* WhL = Wh + (size_t)l * 768 * 256;

    // --- load this thread's 2 register rows (k0..k0+63 each) ---
    const int rrA = rg * 96 + lane * 3;
    float4 w0[16], w1[16];
    {
        int r0 = rrA + 0, r1 = rrA + 1;
        const float4* p0 = reinterpret_cast<const float4*>(
            WhL + (size_t)((r0 >> 6) * 256 + rank * 64 + (r0 & 63)) * 256 + k0);
        const float4* p1 = reinterpret_cast<const float4*>(
            WhL + (size_t)((r1 >> 6) * 256 + rank * 64 + (r1 & 63)) * 256 + k0);
#pragma unroll
        for (int q = 0; q < 16; q++) { w0[q] = p0[q]; w1[q] = p1[q]; }
    }

    // --- cooperative fill of the 3rd-row smem plane: w3[rg][k][lane] ---
    for (int i = tid; i < 2 * 256 * 32; i += SC_THREADS) {
        int rg_ = i >> 13;
        int rem = i & 8191;
        int k   = rem >> 5;
        int ln  = rem & 31;
        int rr  = rg_ * 96 + ln * 3 + 2;
        sw3[i] = WhL[(size_t)((rr >> 6) * 256 + rank * 64 + (rr & 63)) * 256 + k];
    }
    for (int i = tid; i < 2 * 256 * 4; i += SC_THREADS) hbuf[i] = 0.f;

    float bhv = 0.f;
    if (tid < 192) bhv = bh[l * 768 + gi * 256 + hi];

    __syncthreads();
    cluster_barrier();

    const uint32_t hbuf_saddr = (uint32_t)__cvta_generic_to_shared(hbuf);
    float4* part4 = reinterpret_cast<float4*>(part);

    float hprev0 = 0.f, hprev1 = 0.f;
    int p = 0;

    for (int step = 0; step < T_LEN; step++) {
        const int t = dir ? (T_LEN - 1 - step) : step;

        // gx prefetch for combine phase (latency hidden under the dot)
        float gx[4];
        if (tid < 192) {
            const size_t base = ((((size_t)t * LAY + l) * 3 + gi) * BSZ + b0) * HID + hi;
#pragma unroll
            for (int b = 0; b < 4; b++) gx[b] = __ldg(g_gx + base + (size_t)b * HID);
        }

        // --- split-K dot: 3 rows x 4 batches over 64 k ---
        ull a00 = 0, a01v = 0, a10 = 0, a11v = 0, a20 = 0, a21v = 0;
        {
            const ulonglong2* hp = reinterpret_cast<const ulonglong2*>(hbuf)
                                   + p * 256 + k0;
            const float* w3p = sw3 + ((rg << 8) + k0) * 32 + lane;
            const float* f0 = reinterpret_cast<const float*>(w0);
            const float* f1 = reinterpret_cast<const float*>(w1);
#pragma unroll
            for (int kk = 0; kk < 64; kk++) {
                ulonglong2 hk = hp[kk];
                float v2 = w3p[kk << 5];
                ull s0 = splat2(f0[kk]);
                ull s1 = splat2(f1[kk]);
                ull s2 = splat2(v2);
                ffma2(a00, s0, hk.x); ffma2(a01v, s0, hk.y);
                ffma2(a10, s1, hk.x); ffma2(a11v, s1, hk.y);
                ffma2(a20, s2, hk.x); ffma2(a21v, s2, hk.y);
            }
        }
        {
            float2 u, v;
            u = unpack2(a00); v = unpack2(a01v);
            part4[kc * 192 + rrA + 0] = make_float4(u.x, u.y, v.x, v.y);
            u = unpack2(a10); v = unpack2(a11v);
            part4[kc * 192 + rrA + 1] = make_float4(u.x, u.y, v.x, v.y);
            u = unpack2(a20); v = unpack2(a21v);
            part4[kc * 192 + rrA + 2] = make_float4(u.x, u.y, v.x, v.y);
        }
        __syncthreads();

        // --- combine: reduce split-K, gate nonlinearity, exchange ---
        float v0 = 0.f, v1 = 0.f;
        if (tid < 192) {
            float4 q0 = part4[0 * 192 + tid];
            float4 q1 = part4[1 * 192 + tid];
            float4 q2 = part4[2 * 192 + tid];
            float4 q3 = part4[3 * 192 + tid];
            float acc[4];
            acc[0] = (q0.x + q1.x) + (q2.x + q3.x) + bhv;
            acc[1] = (q0.y + q1.y) + (q2.y + q3.y) + bhv;
            acc[2] = (q0.z + q1.z) + (q2.z + q3.z) + bhv;
            acc[3] = (q0.w + q1.w) + (q2.w + q3.w) + bhv;

            if (gi == 0) {
                float r0 = sig_fast(gx[0] + acc[0]);
                float r1 = sig_fast(gx[1] + acc[1]);
                float r2 = sig_fast(gx[2] + acc[2]);
                float r3 = sig_fast(gx[3] + acc[3]);
                v0 = r0; v1 = r1;
                ex_r[2 * 64 + li] = r2; ex_r[3 * 64 + li] = r3;
            } else if (gi == 1) {
                float z0 = sig_fast(gx[0] + acc[0]);
                float z1 = sig_fast(gx[1] + acc[1]);
                float z2 = sig_fast(gx[2] + acc[2]);
                float z3 = sig_fast(gx[3] + acc[3]);
                v0 = z2; v1 = z3;
                ex_z[0 * 64 + li] = z0; ex_z[1 * 64 + li] = z1;
            } else {
#pragma unroll
                for (int b = 0; b < 4; b++) {
                    ex_xn[b * 64 + li] = gx[b] + acc[b];   // xn + hn pre-tanh w/o r
                    ex_hn[b * 64 + li] = acc[b];
                }
                // NOTE: tanh needs xn + r*hn, so store xn separately:
                // ex_xn holds gx (xn), ex_hn holds acc (hn)
                for (int b = 0; b < 4; b++) ex_xn[b * 64 + li] = gx[b];
            }
        }
        __syncthreads();

        // --- finish h_new: gi0 handles b0,b1 ; gi1 handles b2,b3 ---
        if (tid < 128) {
            const int ba = (gi == 0) ? 0 : 2;
            float r_a, r_b, z_a, z_b;
            if (gi == 0) { r_a = v0; r_b = v1; z_a = ex_z[0 * 64 + li]; z_b = ex_z[1 * 64 + li]; }
            else         { r_a = ex_r[2 * 64 + li]; r_b = ex_r[3 * 64 + li]; z_a = v0; z_b = v1; }

            const float n_a = tanh_fast(ex_xn[(ba + 0) * 64 + li] + r_a * ex_hn[(ba + 0) * 64 + li]);
            const float n_b = tanh_fast(ex_xn[(ba + 1) * 64 + li] + r_b * ex_hn[(ba + 1) * 64 + li]);
            const float h_a = (1.f - z_a) * n_a + z_a * hprev0;
            const float h_b = (1.f - z_b) * n_b + z_b * hprev1;
            hprev0 = h_a; hprev1 = h_b;

            const size_t obase = ((size_t)t * LAY + l) * (2 * HID) + dir * HID + hi;
            out[(size_t)(b0 + ba + 0) * (T_LEN * LAY * 2 * HID) + obase] = h_a;
            out[(size_t)(b0 + ba + 1) * (T_LEN * LAY * 2 * HID) + obase] = h_b;

            const uint32_t la = hbuf_saddr
                + (uint32_t)((((1 - p) * 256 + hi) * 4 + ba) * 4);
#pragma unroll
            for (int r2 = 0; r2 < 4; r2++) st_cluster_v2(la, r2, h_a, h_b);
        }
        cluster_barrier();
        p ^= 1;
    }
}

// ---------------------------------------------------------------------------
extern "C" void kernel_launch(void* const* d_in, const int* in_sizes, int n_in,
                              void* d_out, int out_size)
{
    (void)in_sizes; (void)n_in; (void)out_size;
    const float* x  = (const float*)d_in[0];
    const float* Wx = (const float*)d_in[1];
    const float* Wh = (const float*)d_in[2];
    const float* bx = (const float*)d_in[3];
    const float* bh = (const float*)d_in[4];
    float* out = (float*)d_out;

    const int smem1 = 2 * 64 * APAD * 4;                                     // 133,120 B
    const int smem2 = (2*256*32 + 4*192*4 + 2*256*4 + 4*256) * 4;            //  90,112 B

    cudaFuncSetAttribute(gx_gemm_kernel, cudaFuncAttributeMaxDynamicSharedMemorySize, smem1);
    cudaFuncSetAttribute(gru_scan_kernel, cudaFuncAttributeMaxDynamicSharedMemorySize, smem2);

    dim3 grid1(1536 / 64, 128);
    gx_gemm_kernel<<<grid1, 256, smem1>>>(x, Wx, bx);

    gru_scan_kernel<<<128, SC_THREADS, smem2>>>(Wh, bh, out);
}